// round 7
// baseline (speedup 1.0000x reference)
#include <cuda_runtime.h>
#include <cstdint>

// Propagation (B=4, N=4096, D=256):
//   S = val @ val^T ; E = S/(1+|S|) ; out[:,:,:256] = E @ val ; out[:,:,256] = E @ state
// Fused flash-style, fp32, packed f32x2 FMA, register-prefetched j-tiles + state.
//
// CTA = (batch, 64-row i-tile), loop over 64-row j-tiles.
//  GEMM1: 8x32 thread grid, 2(i) x 8(j) register tile, fma.rn.f32x2 packed over j.
//  GEMM2: 16x16 thread grid, 4(i) x 16(d) register tile, d chunk-strided, fma2 over d.
//  J-tile (and state slice) prefetched into registers during GEMMs of the previous
//  tile; stored to Vs; SMEM-transposed into Jt (conflict-free writes).
//  Et uses an XOR swizzle on byte-address bits [4:6] keyed by (j>>3) so the
//  softsign STS.64 writes hit the 2-phase floor instead of 8-way conflicts.

#define B_      4
#define N_      4096
#define D_      256
#define DO_     257
#define TI      64
#define TJ      64
#define THREADS 256

#define PAD_T   64    // pitch of At/Jt [256][PAD_T] (k fixed in-warp -> no pad needed)
#define PAD_V   260   // pitch of Vs [64][PAD_V]
#define PAD_E   68    // pitch of Et [64][PAD_E] (mult of 4: float4-aligned rows)

#define SM_FLOATS (2 * 256 * PAD_T + TJ * PAD_V + TJ * PAD_E + TJ)
#define SM_BYTES  (SM_FLOATS * 4)

typedef unsigned long long u64;

__device__ __forceinline__ void fma2(u64 &d, u64 a, u64 b) {
    asm("fma.rn.f32x2 %0, %1, %2, %0;" : "+l"(d) : "l"(a), "l"(b));
}
__device__ __forceinline__ u64 splat2(float x) {
    u64 r; asm("mov.b64 %0, {%1, %1};" : "=l"(r) : "f"(x)); return r;
}
__device__ __forceinline__ void lds_v2u64(u64 &a, u64 &b, uint32_t addr) {
    asm volatile("ld.shared.v2.b64 {%0, %1}, [%2];" : "=l"(a), "=l"(b) : "r"(addr));
}
__device__ __forceinline__ void sts_v2f32(uint32_t addr, float x, float y) {
    asm volatile("st.shared.v2.f32 [%0], {%1, %2};" :: "r"(addr), "f"(x), "f"(y));
}
__device__ __forceinline__ void lds_v4f32(float4 &v, uint32_t addr) {
    asm volatile("ld.shared.v4.f32 {%0, %1, %2, %3}, [%4];"
                 : "=f"(v.x), "=f"(v.y), "=f"(v.z), "=f"(v.w) : "r"(addr));
}
__device__ __forceinline__ float f2lo(u64 u) { return __int_as_float((int)(unsigned)u); }
__device__ __forceinline__ float f2hi(u64 u) { return __int_as_float((int)(unsigned)(u >> 32)); }
__device__ __forceinline__ float ssign(float x) { return __fdividef(x, 1.0f + fabsf(x)); }

// Et swizzle: XOR byte-address bits [4:6] with (j>>3). Write side: (j>>3)=tx
// (varies across lanes -> spreads banks). Read side: j=k uniform -> no effect.
__device__ __forceinline__ uint32_t et_swz(uint32_t byte_off, int j) {
    return byte_off ^ (uint32_t)(((j >> 3) & 7) << 4);
}

__global__ __launch_bounds__(THREADS, 1)
void prop_kernel(const float* __restrict__ val,
                 const float* __restrict__ state,
                 float* __restrict__ out)
{
    extern __shared__ float sm[];
    float* At = sm;                     // [256][PAD_T]  At[d][i]
    float* Jt = At + 256 * PAD_T;       // [256][PAD_T]  Jt[d][j]
    float* Vs = Jt + 256 * PAD_T;       // [TJ][PAD_V]   Vs[j][d]
    float* Et = Vs + TJ * PAD_V;        // [TJ][PAD_E]   Et[j][i] (swizzled)
    float* st = Et + TJ * PAD_E;        // [TJ]

    const uint32_t smb  = (uint32_t)__cvta_generic_to_shared(sm);
    const uint32_t jt_b = smb + 256 * PAD_T * 4;
    const uint32_t vs_b = jt_b + 256 * PAD_T * 4;
    const uint32_t et_b = vs_b + TJ * PAD_V * 4;

    const int tid = threadIdx.x;
    const int b   = blockIdx.x >> 6;
    const int i0  = (blockIdx.x & 63) * TI;

    const float* valb = val   + (size_t)b * N_ * D_;
    const float* stb  = state + (size_t)b * N_;

    const int ra = tid >> 6;      // linear-load: rows ra+4q, float4 chunk rb
    const int rb = tid & 63;

    // -------- prologue: I-tile -> Vs, prefetch j-tile 0 + state, Vs -> At ------
    {
        const float4* src4 = (const float4*)(valb + (size_t)i0 * D_);
        #pragma unroll
        for (int q = 0; q < 16; ++q) {
            float4 v = src4[tid + THREADS * q];
            *(float4*)(Vs + (ra + 4 * q) * PAD_V + 4 * rb) = v;
        }
    }
    float4 r[16];
    float  st_r;
    {
        const float4* s0 = (const float4*)valb;          // tile 0 at j0 = 0
        #pragma unroll
        for (int q = 0; q < 16; ++q) r[q] = s0[tid + THREADS * q];
        st_r = (tid < TJ) ? stb[tid] : 0.0f;
    }
    __syncthreads();
    {
        const int j = tid & 63;
        #pragma unroll
        for (int q = 0; q < 16; ++q) {
            int c = (tid >> 6) * 16 + q;
            float4 v = *(const float4*)(Vs + j * PAD_V + 4 * c);
            At[(4 * c + 0) * PAD_T + j] = v.x;
            At[(4 * c + 1) * PAD_T + j] = v.y;
            At[(4 * c + 2) * PAD_T + j] = v.z;
            At[(4 * c + 3) * PAD_T + j] = v.w;
        }
    }

    const int tx = tid & 7,  ty = tid >> 3;   // GEMM1: i = 2*ty+ii, j = 8*tx+jj
    const int dg = tid & 15, ig = tid >> 4;   // GEMM2: i = 4*ig+ii, d = 64c+4*dg+e

    u64 acc2[4][8];
    #pragma unroll
    for (int a = 0; a < 4; ++a)
        #pragma unroll
        for (int c = 0; c < 8; ++c) acc2[a][c] = 0ull;
    float dsp[2] = {0.f, 0.f};

    for (int jt = 0; jt < N_ / TJ; ++jt) {
        __syncthreads();                       // (A) prior consumers of Vs/Jt/Et done

        // ---- store prefetched j-tile -> Vs, prefetched state -> st ----
        #pragma unroll
        for (int q = 0; q < 16; ++q)
            *(float4*)(Vs + (ra + 4 * q) * PAD_V + 4 * rb) = r[q];
        if (tid < TJ) st[tid] = st_r;
        __syncthreads();                       // (B)

        // ---- transpose Vs -> Jt (writes conflict-free) ----
        {
            const int j = tid & 63;
            #pragma unroll
            for (int q = 0; q < 16; ++q) {
                int c = (tid >> 6) * 16 + q;
                float4 v = *(const float4*)(Vs + j * PAD_V + 4 * c);
                Jt[(4 * c + 0) * PAD_T + j] = v.x;
                Jt[(4 * c + 1) * PAD_T + j] = v.y;
                Jt[(4 * c + 2) * PAD_T + j] = v.z;
                Jt[(4 * c + 3) * PAD_T + j] = v.w;
            }
        }
        __syncthreads();                       // (C)

        // ---- issue prefetch of next j-tile + state (covered by GEMM1+GEMM2) ----
        {
            const int jn = (jt + 1) & 63;
            const float4* sn = (const float4*)(valb + (size_t)jn * TJ * D_);
            #pragma unroll
            for (int q = 0; q < 16; ++q) r[q] = sn[tid + THREADS * q];
            if (tid < TJ) st_r = stb[jn * TJ + tid];
        }

        // ---- GEMM1: S[2x8] = val_I . val_J^T over K=256 ----
        u64 s2[2][4];
        #pragma unroll
        for (int jp = 0; jp < 4; ++jp) { s2[0][jp] = 0ull; s2[1][jp] = 0ull; }

        #pragma unroll 8
        for (int k = 0; k < D_; ++k) {
            float2 a2 = *(const float2*)(At + k * PAD_T + 2 * ty);
            u64 b0, b1, b2, b3;
            const uint32_t bad = jt_b + (uint32_t)(k * PAD_T + 8 * tx) * 4u;
            lds_v2u64(b0, b1, bad);
            lds_v2u64(b2, b3, bad + 16u);
            u64 ax = splat2(a2.x);
            fma2(s2[0][0], ax, b0); fma2(s2[0][1], ax, b1);
            fma2(s2[0][2], ax, b2); fma2(s2[0][3], ax, b3);
            u64 ay = splat2(a2.y);
            fma2(s2[1][0], ay, b0); fma2(s2[1][1], ay, b1);
            fma2(s2[1][2], ay, b2); fma2(s2[1][3], ay, b3);
        }

        // ---- softsign -> Et[j][i] (swizzled), delta_state partials ----
        #pragma unroll
        for (int jp = 0; jp < 4; ++jp) {
            const float el0 = ssign(f2lo(s2[0][jp]));
            const float eh0 = ssign(f2hi(s2[0][jp]));
            const float el1 = ssign(f2lo(s2[1][jp]));
            const float eh1 = ssign(f2hi(s2[1][jp]));
            const int   jl  = 8 * tx + 2 * jp;
            const float sl  = st[jl], sh = st[jl + 1];
            dsp[0] = fmaf(eh0, sh, fmaf(el0, sl, dsp[0]));
            dsp[1] = fmaf(eh1, sh, fmaf(el1, sl, dsp[1]));
            sts_v2f32(et_b + et_swz((uint32_t)(jl       * PAD_E + 2 * ty) * 4u, jl),
                      el0, el1);
            sts_v2f32(et_b + et_swz((uint32_t)((jl + 1) * PAD_E + 2 * ty) * 4u, jl + 1),
                      eh0, eh1);
        }
        __syncthreads();                       // (D)

        // ---- GEMM2: O[4x16] += E . val_J over K=64 ----
        #pragma unroll 2
        for (int k = 0; k < TJ; ++k) {
            float4 e4;
            lds_v4f32(e4, et_b + et_swz((uint32_t)(k * PAD_E + 4 * ig) * 4u, k));
            u64 v2[8];
            const uint32_t vad = vs_b + (uint32_t)(k * PAD_V + 4 * dg) * 4u;
            lds_v2u64(v2[0], v2[1], vad);
            lds_v2u64(v2[2], v2[3], vad + 64 * 4);
            lds_v2u64(v2[4], v2[5], vad + 128 * 4);
            lds_v2u64(v2[6], v2[7], vad + 192 * 4);
            u64 e2;
            e2 = splat2(e4.x);
            #pragma unroll
            for (int p = 0; p < 8; ++p) fma2(acc2[0][p], e2, v2[p]);
            e2 = splat2(e4.y);
            #pragma unroll
            for (int p = 0; p < 8; ++p) fma2(acc2[1][p], e2, v2[p]);
            e2 = splat2(e4.z);
            #pragma unroll
            for (int p = 0; p < 8; ++p) fma2(acc2[2][p], e2, v2[p]);
            e2 = splat2(e4.w);
            #pragma unroll
            for (int p = 0; p < 8; ++p) fma2(acc2[3][p], e2, v2[p]);
        }
    }

    // ---------------- epilogue: delta_val ----------------
    float* outb = out + (size_t)b * N_ * DO_;
    #pragma unroll
    for (int ii = 0; ii < 4; ++ii) {
        float* orow = outb + (size_t)(i0 + 4 * ig + ii) * DO_;
        #pragma unroll
        for (int c = 0; c < 4; ++c) {
            #pragma unroll
            for (int h = 0; h < 2; ++h) {
                u64 u = acc2[ii][2 * c + h];
                int d0 = 64 * c + 4 * dg + 2 * h;   // DO_=257 odd: scalar stores
                orow[d0 + 0] = f2lo(u);
                orow[d0 + 1] = f2hi(u);
            }
        }
    }

    // ---------------- epilogue: delta_state (reduce over 8 tx lanes) ---------
    #pragma unroll
    for (int off = 1; off < 8; off <<= 1) {
        dsp[0] += __shfl_xor_sync(0xFFFFFFFFu, dsp[0], off);
        dsp[1] += __shfl_xor_sync(0xFFFFFFFFu, dsp[1], off);
    }
    if (tx == 0) {
        outb[(size_t)(i0 + 2 * ty + 0) * DO_ + 256] = dsp[0];
        outb[(size_t)(i0 + 2 * ty + 1) * DO_ + 256] = dsp[1];
    }
}

extern "C" void kernel_launch(void* const* d_in, const int* in_sizes, int n_in,
                              void* d_out, int out_size)
{
    const float* val   = (const float*)d_in[0];   // [4,4096,256] f32
    const float* state = (const float*)d_in[1];   // [4,4096]     f32
    float*       out   = (float*)d_out;           // [4,4096,257] f32

    cudaFuncSetAttribute(prop_kernel,
                         cudaFuncAttributeMaxDynamicSharedMemorySize, SM_BYTES);
    prop_kernel<<<B_ * (N_ / TI), THREADS, SM_BYTES>>>(val, state, out);
}

// round 15
// speedup vs baseline: 4.7111x; 4.7111x over previous
#include <cuda_runtime.h>
#include <cuda_bf16.h>
#include <cstdint>

// Propagation via mma.sync HMMA (compute_103-safe; tcgen05 is rejected by the
// harness's compute_103 virtual-arch build). bf16 hi/lo split, 3 passes/GEMM.
//   S = Vi.Vj^T ; E = softsign(S) ; O += E.Vj ; ds += E.state
// CTA = (batch, 128-row i-tile); 64 j-tiles. O in registers (128 f32/lane).
// One SMEM Vj copy serves both GEMMs: ldmatrix x4 (rows=j) for GEMM1 B,
// ldmatrix x4.trans (rows=j) for GEMM2 B. Per-row XOR-16B swizzle everywhere.

typedef unsigned long long u64;
typedef uint32_t u32;

#define B_      4
#define N_      4096
#define D_      256
#define DO_     257
#define TI      128
#define TJ      64
#define THREADS 256
#define NTILES  (N_ / TJ)

// SMEM layout (bytes). Row pitches: Vi/Vj 512B (256 bf16), E 128B (64 bf16).
#define OFF_VIH 0
#define OFF_VIL (128 * 512)            // 65536
#define OFF_VJH (2 * 128 * 512)        // 131072
#define OFF_VJL (OFF_VJH + 64 * 512)   // 163840
#define OFF_EH  (OFF_VJL + 64 * 512)   // 196608
#define OFF_EL  (OFF_EH + 128 * 128)   // 212992
#define OFF_ST  (OFF_EL + 128 * 128)   // 229376
#define OFF_DS  OFF_EH                  // reused after last GEMM2 (256 f32)
#define SM_BYTES (OFF_ST + 64 * 4)      // 229632 <= 232448 max

#define LDSM4(r, addr) \
    asm volatile("ldmatrix.sync.aligned.m8n8.x4.shared.b16 {%0,%1,%2,%3}, [%4];" \
        : "=r"((r)[0]), "=r"((r)[1]), "=r"((r)[2]), "=r"((r)[3]) : "r"(addr))
#define LDSM4T(r, addr) \
    asm volatile("ldmatrix.sync.aligned.m8n8.x4.trans.shared.b16 {%0,%1,%2,%3}, [%4];" \
        : "=r"((r)[0]), "=r"((r)[1]), "=r"((r)[2]), "=r"((r)[3]) : "r"(addr))
#define MMA_BF16(c, a, b0, b1) \
    asm volatile("mma.sync.aligned.m16n8k16.row.col.f32.bf16.bf16.f32 " \
        "{%0,%1,%2,%3}, {%4,%5,%6,%7}, {%8,%9}, {%0,%1,%2,%3};" \
        : "+f"((c)[0]), "+f"((c)[1]), "+f"((c)[2]), "+f"((c)[3]) \
        : "r"((a)[0]), "r"((a)[1]), "r"((a)[2]), "r"((a)[3]), "r"(b0), "r"(b1))

__device__ __forceinline__ u32 bfbits(float x) {
    return (u32)__bfloat16_as_ushort(__float2bfloat16(x));
}
__device__ __forceinline__ float frombits(u32 h) { return __uint_as_float(h << 16); }
__device__ __forceinline__ float ssign(float x) { return __fdividef(x, 1.0f + fabsf(x)); }

// Swizzled byte offsets (XOR bits [4:6] with row&7 -> conflict-free ldmatrix).
__device__ __forceinline__ u32 vswz(int row, u32 cb) {   // 512B-pitch tiles
    return (u32)(row * 512) + (cb ^ (u32)((row & 7) << 4));
}
__device__ __forceinline__ u32 eswz(int row, u32 cb) {   // 128B-pitch tiles
    return (u32)(row * 128) + (cb ^ (u32)((row & 7) << 4));
}

__device__ __forceinline__ void sts64(u32 a, u64 v) {
    asm volatile("st.shared.b64 [%0], %1;" :: "r"(a), "l"(v) : "memory");
}
__device__ __forceinline__ void sts32(u32 a, u32 v) {
    asm volatile("st.shared.b32 [%0], %1;" :: "r"(a), "r"(v) : "memory");
}

// float4 -> packed bf16 hi x4 / lo x4.
__device__ __forceinline__ void cvt_split(float4 v, u64& hp, u64& lp) {
    u32 h0 = bfbits(v.x), h1 = bfbits(v.y), h2 = bfbits(v.z), h3 = bfbits(v.w);
    u32 l0 = bfbits(v.x - frombits(h0)), l1 = bfbits(v.y - frombits(h1));
    u32 l2 = bfbits(v.z - frombits(h2)), l3 = bfbits(v.w - frombits(h3));
    hp = (u64)h0 | ((u64)h1 << 16) | ((u64)h2 << 32) | ((u64)h3 << 48);
    lp = (u64)l0 | ((u64)l1 << 16) | ((u64)l2 << 32) | ((u64)l3 << 48);
}

__global__ __launch_bounds__(THREADS, 1)
void prop_mma(const float* __restrict__ val,
              const float* __restrict__ state,
              float* __restrict__ out)
{
    extern __shared__ char smem[];
    const u32 smb = (u32)__cvta_generic_to_shared(smem);
    const int tid  = threadIdx.x;
    const int wid  = tid >> 5;
    const int lane = tid & 31;

    const int b  = blockIdx.x >> 5;              // grid = 4 * 32
    const int i0 = (blockIdx.x & 31) * TI;
    const float* valb = val   + (size_t)b * N_ * D_;
    const float* stb  = state + (size_t)b * N_;

    // Warp tiling: phase1 S[128x64]: warp (iblk 0-3) x (jblk 0-1) -> 32i x 32j.
    //              phase2 O[128x256]: same iblk, d-half = jblk -> 32i x 128d.
    const int iblk = wid & 3, jblk = wid >> 2;
    const int i0w = iblk * 32, j0w = jblk * 32;
    const int lr = lane & 15, lc = lane >> 4;    // ldmatrix row / 16B-col-block
    const int qr = lane >> 2, qc = lane & 3;     // mma accum row / col-pair

    float* stp = (float*)(smem + OFF_ST);

    // ---- prologue: Vi -> SMEM hi/lo ----
    #pragma unroll
    for (int q = 0; q < 32; ++q) {
        int g = tid + THREADS * q;               // 8192 float4 chunks
        int i = g >> 6, c4 = g & 63;
        float4 v = ((const float4*)(valb + (size_t)(i0 + i) * D_))[c4];
        u64 hp, lp;
        cvt_split(v, hp, lp);
        u32 a = vswz(i, (u32)(8 * c4));
        sts64(smb + OFF_VIH + a, hp);
        sts64(smb + OFF_VIL + a, lp);
    }
    float st_r = (tid < TJ) ? stb[tid] : 0.0f;   // tile 0 state

    float oacc[2][16][4];
    #pragma unroll
    for (int mi = 0; mi < 2; ++mi)
        #pragma unroll
        for (int n8 = 0; n8 < 16; ++n8)
            #pragma unroll
            for (int e = 0; e < 4; ++e) oacc[mi][n8][e] = 0.0f;
    float dsp[2][2] = {{0.f, 0.f}, {0.f, 0.f}};

    for (int jt = 0; jt < NTILES; ++jt) {
        __syncthreads();                         // (A) prior readers of Vj/E done

        // ---- Vj tile -> SMEM hi/lo + state slice ----
        {
            const float4* src4 = (const float4*)(valb + (size_t)jt * TJ * D_);
            #pragma unroll
            for (int q = 0; q < 16; ++q) {
                int g = tid + THREADS * q;       // 4096 chunks = 64 rows x 64
                int j = g >> 6, c4 = g & 63;
                float4 v = src4[g];
                u64 hp, lp;
                cvt_split(v, hp, lp);
                u32 a = vswz(j, (u32)(8 * c4));
                sts64(smb + OFF_VJH + a, hp);
                sts64(smb + OFF_VJL + a, lp);
            }
            if (tid < TJ) stp[tid] = st_r;
        }
        __syncthreads();                         // (B)
        {
            const int jn = (jt + 1) & (NTILES - 1);
            if (tid < TJ) st_r = stb[jn * TJ + tid];
        }

        // ---- GEMM1: S[32x32/warp] = Vi . Vj^T over K=256, 3 passes ----
        float sacc[2][4][4];
        #pragma unroll
        for (int mi = 0; mi < 2; ++mi)
            #pragma unroll
            for (int nj = 0; nj < 4; ++nj)
                #pragma unroll
                for (int e = 0; e < 4; ++e) sacc[mi][nj][e] = 0.0f;

        #pragma unroll 4
        for (int ks = 0; ks < 16; ++ks) {
            const u32 cb = (u32)(ks * 32 + lc * 16);
            u32 ah[2][4], al[2][4];
            #pragma unroll
            for (int mi = 0; mi < 2; ++mi) {
                int rowA = i0w + 16 * mi + lr;
                LDSM4(ah[mi], smb + OFF_VIH + vswz(rowA, cb));
                LDSM4(al[mi], smb + OFF_VIL + vswz(rowA, cb));
            }
            u32 bh[2][4], bl[2][4];
            #pragma unroll
            for (int jh = 0; jh < 2; ++jh) {
                int rowB = j0w + 16 * jh + lr;
                LDSM4(bh[jh], smb + OFF_VJH + vswz(rowB, cb));
                LDSM4(bl[jh], smb + OFF_VJL + vswz(rowB, cb));
            }
            #pragma unroll
            for (int mi = 0; mi < 2; ++mi)
                #pragma unroll
                for (int jh = 0; jh < 2; ++jh)
                    #pragma unroll
                    for (int t = 0; t < 2; ++t) {
                        float* sc = sacc[mi][jh * 2 + t];
                        MMA_BF16(sc, ah[mi], bh[jh][t], bh[jh][t + 2]); // hi.hi
                        MMA_BF16(sc, ah[mi], bl[jh][t], bl[jh][t + 2]); // hi.lo
                        MMA_BF16(sc, al[mi], bh[jh][t], bh[jh][t + 2]); // lo.hi
                    }
        }

        // ---- softsign -> E SMEM (hi/lo), ds partials in registers ----
        #pragma unroll
        for (int mi = 0; mi < 2; ++mi)
            #pragma unroll
            for (int nj = 0; nj < 4; ++nj) {
                const int j0 = j0w + 8 * nj + 2 * qc;
                const int r0 = i0w + 16 * mi + qr;
                float e00 = ssign(sacc[mi][nj][0]);
                float e01 = ssign(sacc[mi][nj][1]);
                float e10 = ssign(sacc[mi][nj][2]);
                float e11 = ssign(sacc[mi][nj][3]);
                const float s0 = stp[j0], s1 = stp[j0 + 1];
                dsp[mi][0] = fmaf(e01, s1, fmaf(e00, s0, dsp[mi][0]));
                dsp[mi][1] = fmaf(e11, s1, fmaf(e10, s0, dsp[mi][1]));
                u32 b00 = bfbits(e00), b01 = bfbits(e01);
                u32 b10 = bfbits(e10), b11 = bfbits(e11);
                u32 L00 = bfbits(e00 - frombits(b00)), L01 = bfbits(e01 - frombits(b01));
                u32 L10 = bfbits(e10 - frombits(b10)), L11 = bfbits(e11 - frombits(b11));
                u32 a0 = eswz(r0,     (u32)(2 * j0));
                u32 a1 = eswz(r0 + 8, (u32)(2 * j0));
                sts32(smb + OFF_EH + a0, b00 | (b01 << 16));
                sts32(smb + OFF_EL + a0, L00 | (L01 << 16));
                sts32(smb + OFF_EH + a1, b10 | (b11 << 16));
                sts32(smb + OFF_EL + a1, L10 | (L11 << 16));
            }
        __syncthreads();                         // (C) E visible

        // ---- GEMM2: O[32x128/warp] += E . Vj over K=64, 3 passes ----
        #pragma unroll
        for (int ks = 0; ks < 4; ++ks) {
            const u32 ecb = (u32)(ks * 32 + lc * 16);
            u32 eh[2][4], el[2][4];
            #pragma unroll
            for (int mi = 0; mi < 2; ++mi) {
                int rowE = i0w + 16 * mi + lr;
                LDSM4(eh[mi], smb + OFF_EH + eswz(rowE, ecb));
                LDSM4(el[mi], smb + OFF_EL + eswz(rowE, ecb));
            }
            #pragma unroll
            for (int db = 0; db < 8; ++db) {
                u32 vh[4], vl[4];
                int rowV = ks * 16 + lr;
                u32 vcb = (u32)(jblk * 256 + db * 32 + lc * 16);
                LDSM4T(vh, smb + OFF_VJH + vswz(rowV, vcb));
                LDSM4T(vl, smb + OFF_VJL + vswz(rowV, vcb));
                #pragma unroll
                for (int mi = 0; mi < 2; ++mi)
                    #pragma unroll
                    for (int dt = 0; dt < 2; ++dt) {
                        float* oc = oacc[mi][2 * db + dt];
                        MMA_BF16(oc, eh[mi], vh[2 * dt], vh[2 * dt + 1]); // hi.hi
                        MMA_BF16(oc, eh[mi], vl[2 * dt], vl[2 * dt + 1]); // hi.lo
                        MMA_BF16(oc, el[mi], vh[2 * dt], vh[2 * dt + 1]); // lo.hi
                    }
            }
        }
    }

    // ---- epilogue: O -> out[:, :256] ----
    float* outb = out + (size_t)b * N_ * DO_;
    #pragma unroll
    for (int mi = 0; mi < 2; ++mi)
        #pragma unroll
        for (int n8 = 0; n8 < 16; ++n8) {
            const int d   = jblk * 128 + 8 * n8 + 2 * qc;
            const int row = i0 + i0w + 16 * mi + qr;
            float* o0 = outb + (size_t)row * DO_ + d;
            float* o1 = outb + (size_t)(row + 8) * DO_ + d;
            o0[0] = oacc[mi][n8][0];
            o0[1] = oacc[mi][n8][1];
            o1[0] = oacc[mi][n8][2];
            o1[1] = oacc[mi][n8][3];
        }

    // ---- delta_state: quad-reduce, per-jhalf buffers, final sum ----
    __syncthreads();                             // all GEMM2 reads of E done
    float* dsb = (float*)(smem + OFF_DS);        // [2][128]
    #pragma unroll
    for (int mi = 0; mi < 2; ++mi)
        #pragma unroll
        for (int rh = 0; rh < 2; ++rh) {
            float v = dsp[mi][rh];
            v += __shfl_xor_sync(0xFFFFFFFFu, v, 1);
            v += __shfl_xor_sync(0xFFFFFFFFu, v, 2);
            if (qc == 0)
                dsb[jblk * TI + i0w + 16 * mi + 8 * rh + qr] = v;
        }
    __syncthreads();
    if (tid < TI)
        outb[(size_t)(i0 + tid) * DO_ + 256] = dsb[tid] + dsb[TI + tid];
}

extern "C" void kernel_launch(void* const* d_in, const int* in_sizes, int n_in,
                              void* d_out, int out_size)
{
    const float* val   = (const float*)d_in[0];   // [4,4096,256] f32
    const float* state = (const float*)d_in[1];   // [4,4096]     f32
    float*       out   = (float*)d_out;           // [4,4096,257] f32

    cudaFuncSetAttribute(prop_mma,
                         cudaFuncAttributeMaxDynamicSharedMemorySize, SM_BYTES);
    prop_mma<<<B_ * (N_ / TI), THREADS, SM_BYTES>>>(val, state, out);
}